// round 12
// baseline (speedup 1.0000x reference)
#include <cuda_runtime.h>
#include <math.h>

#define LL 512
#define CS 384
#define CZ 256
#define PW 1152
#define SH 3648
#define WLL 0.57735026918962576f
#define WCC 0.23570226039551584f

typedef unsigned long long u64;
__device__ __forceinline__ u64 dup2(float a){ u64 r; asm("mov.b64 %0,{%1,%1};" : "=l"(r) : "f"(a)); return r; }
__device__ __forceinline__ u64 pack2(float lo, float hi){ u64 r; asm("mov.b64 %0,{%1,%2};" : "=l"(r) : "f"(lo), "f"(hi)); return r; }
__device__ __forceinline__ void unpack2(u64 v, float& lo, float& hi){ asm("mov.b64 {%0,%1},%2;" : "=f"(lo), "=f"(hi) : "l"(v)); }
__device__ __forceinline__ void ffma2(u64& d, u64 a, u64 b){ asm("fma.rn.f32x2 %0,%1,%2,%0;" : "+l"(d) : "l"(a), "l"(b)); }

__device__ float g_Wcat[CS * PW];
__device__ float g_proj[LL * PW];   // [q 0|k 192|v 384|qp 576|kp 720|vp 864]
__device__ float g_R[LL * 9];
__device__ float g_t[LL * 3];
__device__ float g_coef[12];
__device__ float g_qpp[LL * 144];
__device__ float g_kT[192 * LL];
__device__ float g_vT[192 * LL];
__device__ float g_kppT[144 * LL];
__device__ float g_vppT[288 * LL];
__device__ float g_Bt[12 * LL * LL];    // bias logits, head-major [h][i*512+j]
__device__ float g_A[LL * 12 * LL];     // softmaxed attention [i][h][j]
__device__ float g_shid[LL * SH];
__device__ float g_parts[6 * LL * CS];
__device__ float g_s1[LL * CS];
__device__ float g_h1[LL * CS];
__device__ float g_h2[LL * CS];

// merged: weight packing + quat prep + bias GEMM (128 rows per CTA, 2048 CTAs)
__global__ __launch_bounds__(256) void prep_bias(
    const float* __restrict__ z, const float* __restrict__ Wb,
    const float* __restrict__ Wq, const float* __restrict__ Wk,
    const float* __restrict__ Wv, const float* __restrict__ Wqp,
    const float* __restrict__ Wkp, const float* __restrict__ Wvp,
    const float* __restrict__ quat, const float* __restrict__ trsl,
    const float* __restrict__ scale)
{
    int tid = threadIdx.x;
    int gid = blockIdx.x * 256 + tid;

    // ---- pack / prep (scattered, independent) ----
    if (gid < CS * PW) {
        int r = gid / PW, c = gid - r * PW;
        float v;
        if      (c < 192)  v = Wq [r*192 + c];
        else if (c < 384)  v = Wk [r*192 + c-192];
        else if (c < 576)  v = Wv [r*192 + c-384];
        else if (c < 720)  v = Wqp[r*144 + c-576];
        else if (c < 864)  v = Wkp[r*144 + c-720];
        else               v = Wvp[r*288 + c-864];
        g_Wcat[gid] = v;
    }
    if (gid < LL) {
        float w = quat[gid*4], x = quat[gid*4+1], y = quat[gid*4+2], zz = quat[gid*4+3];
        float inv = rsqrtf(w*w + x*x + y*y + zz*zz);
        w *= inv; x *= inv; y *= inv; zz *= inv;
        float* R = g_R + gid*9;
        R[0]=1.f-2.f*(y*y+zz*zz); R[1]=2.f*(x*y-w*zz);     R[2]=2.f*(x*zz+w*y);
        R[3]=2.f*(x*y+w*zz);      R[4]=1.f-2.f*(x*x+zz*zz); R[5]=2.f*(y*zz-w*x);
        R[6]=2.f*(x*zz-w*y);      R[7]=2.f*(y*zz+w*x);      R[8]=1.f-2.f*(x*x+y*y);
        g_t[gid*3]=trsl[gid*3]; g_t[gid*3+1]=trsl[gid*3+1]; g_t[gid*3+2]=trsl[gid*3+2];
    }
    if (gid < 12) g_coef[gid] = 0.5f * WCC * log1pf(expf(scale[gid]));

    // ---- bias GEMM: rows [row0, row0+128) ----
    __shared__ u64 sW[CZ * 6];          // 12 KB
    __shared__ float sAz[128][33];      // 16.9 KB
    int row0 = blockIdx.x * 128;
    int q = tid & 127, hp = tid >> 7;   // one row per thread; hp picks 3 head-pairs

    for (int x = tid; x < CZ*6; x += 256) {
        int c = x / 6, p = x - c*6;
        sW[x] = pack2(Wb[c*12 + 2*p], Wb[c*12 + 2*p + 1]);
    }

    u64 acc[3] = {};
    for (int ch = 0; ch < 8; ch++) {
        __syncthreads();
        #pragma unroll
        for (int t0 = 0; t0 < 4; t0++) {
            int idx = tid + t0 * 256;       // 1024 float4
            int row = idx >> 3, c4 = idx & 7;
            float4 v = *(const float4*)(z + (size_t)(row0 + row) * CZ + ch*32 + c4*4);
            sAz[row][c4*4+0] = v.x; sAz[row][c4*4+1] = v.y;
            sAz[row][c4*4+2] = v.z; sAz[row][c4*4+3] = v.w;
        }
        __syncthreads();
        #pragma unroll 4
        for (int c = 0; c < 32; c++) {
            int cc = ch*32 + c;
            u64 d0 = dup2(sAz[q][c]);
            ffma2(acc[0], d0, sW[cc*6 + hp*3 + 0]);
            ffma2(acc[1], d0, sW[cc*6 + hp*3 + 1]);
            ffma2(acc[2], d0, sW[cc*6 + hp*3 + 2]);
        }
    }
    #pragma unroll
    for (int p = 0; p < 3; p++) {
        float lo, hi;
        unpack2(acc[p], lo, hi);
        g_Bt[(size_t)(hp*6+2*p  )*(LL*LL) + row0 + q] = lo;
        g_Bt[(size_t)(hp*6+2*p+1)*(LL*LL) + row0 + q] = hi;
    }
}

__global__ void transform()
{
    int i = blockIdx.x, pt = threadIdx.x;   // 384 threads
    if (pt < 192) g_kT[pt * LL + i] = g_proj[(size_t)i*PW + 192 + pt];
    else          g_vT[(pt-192) * LL + i] = g_proj[(size_t)i*PW + 384 + (pt-192)];
    if (pt >= 192) return;
    const float* R = g_R + i*9;
    const float* t = g_t + i*3;
    const float* src;
    if (pt < 48)      src = g_proj + (size_t)i*PW + 576 + pt*3;
    else if (pt < 96) src = g_proj + (size_t)i*PW + 720 + (pt-48)*3;
    else              src = g_proj + (size_t)i*PW + 864 + (pt-96)*3;
    float px = src[0], py = src[1], pz = src[2];
    float ox = R[0]*px + R[1]*py + R[2]*pz + t[0];
    float oy = R[3]*px + R[4]*py + R[5]*pz + t[1];
    float oz = R[6]*px + R[7]*py + R[8]*pz + t[2];
    if (pt < 48) {
        float* d = g_qpp + i*144 + pt*3;
        d[0] = ox; d[1] = oy; d[2] = oz;
    } else if (pt < 96) {
        int p = pt - 48;
        g_kppT[(p*3+0)*LL + i] = ox;
        g_kppT[(p*3+1)*LL + i] = oy;
        g_kppT[(p*3+2)*LL + i] = oz;
    } else {
        int p = pt - 96;
        g_vppT[(p*3+0)*LL + i] = ox;
        g_vppT[(p*3+1)*LL + i] = oy;
        g_vppT[(p*3+2)*LL + i] = oz;
    }
}

// 128x64 tile GEMM, 256 threads, 8x4/thread, A pre-duplicated f32x2 in smem
__global__ __launch_bounds__(256) void gemm128(const float* __restrict__ A,
                                               const float* __restrict__ B,
                                               float* __restrict__ C,
                                               int lda, int ldb, int ldc,
                                               int kSlice, int K, int partStride)
{
    __shared__ u64 As[16][128];
    __shared__ float Bs[16][64];
    int n0 = blockIdx.x * 64, m0 = blockIdx.y * 128;
    int k0 = blockIdx.z * kSlice;
    int kend = min(K, k0 + kSlice);
    float* Cc = C + (size_t)blockIdx.z * partStride;
    int tid = threadIdx.x;
    int tx = tid & 15, ty = tid >> 4;
    u64 acc[8][2] = {};
    for (int kt = k0; kt < kend; kt += 16) {
        #pragma unroll
        for (int half = 0; half < 2; half++) {
            int f = tid + half * 256;
            int row = f >> 2, kq = (f & 3) << 2;
            float4 av = *(const float4*)(A + (size_t)(m0 + row) * lda + kt + kq);
            As[kq+0][row] = dup2(av.x);
            As[kq+1][row] = dup2(av.y);
            As[kq+2][row] = dup2(av.z);
            As[kq+3][row] = dup2(av.w);
        }
        {
            int k = tid >> 4, nq = (tid & 15) << 2;
            *(float4*)&Bs[k][nq] = *(const float4*)(B + (size_t)(kt + k) * ldb + n0 + nq);
        }
        __syncthreads();
        #pragma unroll
        for (int kk = 0; kk < 16; kk++) {
            u64 a[8];
            *(ulonglong2*)&a[0] = *(ulonglong2*)&As[kk][ty*8+0];
            *(ulonglong2*)&a[2] = *(ulonglong2*)&As[kk][ty*8+2];
            *(ulonglong2*)&a[4] = *(ulonglong2*)&As[kk][ty*8+4];
            *(ulonglong2*)&a[6] = *(ulonglong2*)&As[kk][ty*8+6];
            ulonglong2 b2 = *(ulonglong2*)&Bs[kk][tx << 2];
            #pragma unroll
            for (int m = 0; m < 8; m++) {
                ffma2(acc[m][0], a[m], b2.x);
                ffma2(acc[m][1], a[m], b2.y);
            }
        }
        __syncthreads();
    }
    #pragma unroll
    for (int m = 0; m < 8; m++) {
        ulonglong2 st; st.x = acc[m][0]; st.y = acc[m][1];
        *(ulonglong2*)(Cc + (size_t)(m0 + ty*8 + m) * ldc + n0 + (tx << 2)) = st;
    }
}

__global__ void combine(const float* __restrict__ parts, int nparts, int partStride,
                        const float* __restrict__ bias, float* __restrict__ out,
                        int total, int N, int relu)
{
    int idx = blockIdx.x * blockDim.x + threadIdx.x;
    if (idx >= total) return;
    float v = parts[idx];
    for (int p = 1; p < nparts; p++) v += parts[(size_t)p * partStride + idx];
    if (bias) v += bias[idx % N];
    if (relu) v = fmaxf(v, 0.f);
    out[idx] = v;
}

__global__ void ln_combine(const float* __restrict__ parts, int nparts, int partStride,
                           const float* __restrict__ bias, const float* __restrict__ resid,
                           const float* __restrict__ gg, const float* __restrict__ bb,
                           float* __restrict__ out)
{
    int i = blockIdx.x, t = threadIdx.x;   // 128 threads
    float v[3];
    #pragma unroll
    for (int k = 0; k < 3; k++) {
        int c = t + k * 128;
        size_t off = (size_t)i * CS + c;
        float x = parts[off];
        for (int p = 1; p < nparts; p++) x += parts[(size_t)p * partStride + off];
        v[k] = x + bias[c] + resid[off];
    }
    float s = v[0]+v[1]+v[2], q = v[0]*v[0]+v[1]*v[1]+v[2]*v[2];
    #pragma unroll
    for (int o = 16; o; o >>= 1) {
        s += __shfl_xor_sync(0xffffffffu, s, o);
        q += __shfl_xor_sync(0xffffffffu, q, o);
    }
    __shared__ float ss[4], sq[4];
    int w = t >> 5, lane = t & 31;
    if (lane == 0) { ss[w] = s; sq[w] = q; }
    __syncthreads();
    if (t == 0) {
        float S = ss[0]+ss[1]+ss[2]+ss[3], Q = sq[0]+sq[1]+sq[2]+sq[3];
        float m = S * (1.f/CS);
        ss[0] = m; sq[0] = rsqrtf(Q*(1.f/CS) - m*m + 1e-5f);
    }
    __syncthreads();
    float m = ss[0], r = sq[0];
    float* o = out + (size_t)i * CS;
    #pragma unroll
    for (int k = 0; k < 3; k++) {
        int c = t + k * 128;
        o[c] = (v[k]-m)*r*gg[c] + bb[c];
    }
}

// attention: logits + softmax + ov/ovp; writes weights to g_A
__global__ __launch_bounds__(256) void attn()
{
    __shared__ float sA[12 * LL];     // 24 KB
    __shared__ float sq[192], sqpp[144], sR[9], st3[3], scoef[12], sOVP[288];

    int i = blockIdx.x, tid = threadIdx.x;
    int lane = tid & 31, w = tid >> 5;

    if (tid < 192) sq[tid] = g_proj[(size_t)i * PW + tid];
    if (tid < 144) sqpp[tid] = g_qpp[i*144 + tid];
    if (tid < 9)   sR[tid] = g_R[i*9 + tid];
    if (tid < 3)   st3[tid] = g_t[i*3 + tid];
    if (tid < 12)  scoef[tid] = g_coef[tid];
    __syncthreads();

    #pragma unroll
    for (int jj = 0; jj < 2; jj++) {
        int j = tid + jj * 256;
        #pragma unroll
        for (int h = 0; h < 12; h++) {
            float qk = 0.f;
            #pragma unroll
            for (int d = 0; d < 16; d++)
                qk = fmaf(sq[h*16+d], g_kT[(h*16+d)*LL + j], qk);
            float d2 = 0.f;
            #pragma unroll
            for (int e = 0; e < 12; e++) {
                float dd = sqpp[h*12+e] - g_kppT[(h*12+e)*LL + j];
                d2 = fmaf(dd, dd, d2);
            }
            float bh = g_Bt[(size_t)h * (LL*LL) + (size_t)i * LL + j];
            sA[h*LL + j] = WLL * (qk * 0.25f + bh - scoef[h] * d2);
        }
    }
    __syncthreads();

    for (int h = w; h < 12; h += 8) {
        float* row = sA + h * LL;
        float m = -1e30f;
        for (int j = lane; j < LL; j += 32) m = fmaxf(m, row[j]);
        #pragma unroll
        for (int o = 16; o; o >>= 1) m = fmaxf(m, __shfl_xor_sync(0xffffffffu, m, o));
        float sum = 0.f;
        for (int j = lane; j < LL; j += 32) {
            float e = __expf(row[j] - m);
            row[j] = e; sum += e;
        }
        #pragma unroll
        for (int o = 16; o; o >>= 1) sum += __shfl_xor_sync(0xffffffffu, sum, o);
        float inv = 1.f / sum;
        for (int j = lane; j < LL; j += 32) row[j] *= inv;
    }
    __syncthreads();

    {
        float* ga = g_A + (size_t)i * 12 * LL;
        for (int x = tid * 4; x < 12 * LL; x += 1024)
            *(float4*)(ga + x) = *(const float4*)&sA[x];
    }

    if (tid < 240) {
        int h = tid / 20, o = (tid % 20) * 2;
        const float* s0;
        if (o < 16) s0 = g_vT + (h*16+o)*LL;
        else        s0 = g_vppT + (h*24+o-16)*LL;
        const float* s1p = s0 + LL;
        const float* ap = sA + h * LL;
        float a0 = 0.f, a1 = 0.f;
        for (int j = 0; j < LL; j += 8) {
            float4 v0a = *(const float4*)(s0 + j),  v0b = *(const float4*)(s0 + j + 4);
            float4 v1a = *(const float4*)(s1p + j), v1b = *(const float4*)(s1p + j + 4);
            float4 aa  = *(const float4*)(ap + j),  ab  = *(const float4*)(ap + j + 4);
            a0 = fmaf(aa.x,v0a.x,fmaf(aa.y,v0a.y,fmaf(aa.z,v0a.z,fmaf(aa.w,v0a.w,a0))));
            a0 = fmaf(ab.x,v0b.x,fmaf(ab.y,v0b.y,fmaf(ab.z,v0b.z,fmaf(ab.w,v0b.w,a0))));
            a1 = fmaf(aa.x,v1a.x,fmaf(aa.y,v1a.y,fmaf(aa.z,v1a.z,fmaf(aa.w,v1a.w,a1))));
            a1 = fmaf(ab.x,v1b.x,fmaf(ab.y,v1b.y,fmaf(ab.z,v1b.z,fmaf(ab.w,v1b.w,a1))));
        }
        float* orow = g_shid + (size_t)i * SH + h * 304;
        if (o < 16) { orow[256+o] = a0; orow[257+o] = a1; }
        else        { sOVP[h*24 + o-16] = a0; sOVP[h*24 + o-15] = a1; }
    }
    __syncthreads();

    if (tid < 96) {
        int h = tid >> 3, vv = tid & 7;
        float gx = sOVP[h*24 + vv*3 + 0] - st3[0];
        float gy = sOVP[h*24 + vv*3 + 1] - st3[1];
        float gz = sOVP[h*24 + vv*3 + 2] - st3[2];
        float lx = sR[0]*gx + sR[3]*gy + sR[6]*gz;
        float ly = sR[1]*gx + sR[4]*gy + sR[7]*gz;
        float lz = sR[2]*gx + sR[5]*gy + sR[8]*gz;
        float* orow = g_shid + (size_t)i * SH + h * 304;
        orow[272 + vv*3 + 0] = lx;
        orow[272 + vv*3 + 1] = ly;
        orow[272 + vv*3 + 2] = lz;
        orow[296 + vv] = sqrtf(lx*lx + ly*ly + lz*lz);
    }
}

// op = a^T @ z per query row, packed f32x2; one CTA per i
__global__ __launch_bounds__(256) void op_gemm(const float* __restrict__ z)
{
    __shared__ float sA[12 * LL];   // 24 KB
    int i = blockIdx.x, tid = threadIdx.x;
    const float* ga = g_A + (size_t)i * 12 * LL;
    for (int x = tid * 4; x < 12 * LL; x += 1024)
        *(float4*)&sA[x] = *(const float4*)(ga + x);
    __syncthreads();

    int h0 = (tid >> 6) * 3;
    int cc = (tid & 63) << 2;
    const float* zp = z + (size_t)i * LL * CZ + cc;
    const float* a0p = sA + (h0+0) * LL;
    const float* a1p = sA + (h0+1) * LL;
    const float* a2p = sA + (h0+2) * LL;
    u64 acc[3][2] = {};
    for (int j = 0; j < LL; j += 4) {
        ulonglong2 zv[4];
        #pragma unroll
        for (int u = 0; u < 4; u++)
            zv[u] = *(const ulonglong2*)(zp + (size_t)(j+u) * CZ);
        float4 a0 = *(const float4*)(a0p + j);
        float4 a1 = *(const float4*)(a1p + j);
        float4 a2 = *(const float4*)(a2p + j);
        float a0v[4] = {a0.x,a0.y,a0.z,a0.w};
        float a1v[4] = {a1.x,a1.y,a1.z,a1.w};
        float a2v[4] = {a2.x,a2.y,a2.z,a2.w};
        #pragma unroll
        for (int u = 0; u < 4; u++) {
            u64 d0 = dup2(a0v[u]), d1 = dup2(a1v[u]), d2 = dup2(a2v[u]);
            ffma2(acc[0][0], zv[u].x, d0); ffma2(acc[0][1], zv[u].y, d0);
            ffma2(acc[1][0], zv[u].x, d1); ffma2(acc[1][1], zv[u].y, d1);
            ffma2(acc[2][0], zv[u].x, d2); ffma2(acc[2][1], zv[u].y, d2);
        }
    }
    float* orow = g_shid + (size_t)i * SH;
    #pragma unroll
    for (int hh = 0; hh < 3; hh++) {
        ulonglong2 st; st.x = acc[hh][0]; st.y = acc[hh][1];
        *(ulonglong2*)(orow + (h0+hh)*304 + cc) = st;
    }
}

extern "C" void kernel_launch(void* const* d_in, const int* in_sizes, int n_in,
                              void* d_out, int out_size)
{
    const float* s    = (const float*)d_in[0];
    const float* z    = (const float*)d_in[1];
    const float* quat = (const float*)d_in[2];
    const float* trsl = (const float*)d_in[3];
    const float* Wq   = (const float*)d_in[4];
    const float* Wk   = (const float*)d_in[5];
    const float* Wv   = (const float*)d_in[6];
    const float* Wqp  = (const float*)d_in[7];
    const float* Wkp  = (const float*)d_in[8];
    const float* Wvp  = (const float*)d_in[9];
    const float* Wb   = (const float*)d_in[10];
    const float* Ws   = (const float*)d_in[11];
    const float* bs   = (const float*)d_in[12];
    const float* scale= (const float*)d_in[13];
    const float* g1   = (const float*)d_in[14];
    const float* b1   = (const float*)d_in[15];
    const float* Wm1  = (const float*)d_in[16];
    const float* bm1  = (const float*)d_in[17];
    const float* Wm2  = (const float*)d_in[18];
    const float* bm2  = (const float*)d_in[19];
    const float* Wm3  = (const float*)d_in[20];
    const float* bm3  = (const float*)d_in[21];
    const float* g2   = (const float*)d_in[22];
    const float* b2   = (const float*)d_in[23];
    float* out = (float*)d_out;

    void *pWcat, *pProj, *pShid, *pParts, *pS1, *pH1, *pH2;
    cudaGetSymbolAddress(&pWcat,  g_Wcat);
    cudaGetSymbolAddress(&pProj,  g_proj);
    cudaGetSymbolAddress(&pShid,  g_shid);
    cudaGetSymbolAddress(&pParts, g_parts);
    cudaGetSymbolAddress(&pS1,    g_s1);
    cudaGetSymbolAddress(&pH1,    g_h1);
    cudaGetSymbolAddress(&pH2,    g_h2);
    float* Wcat = (float*)pWcat;  float* proj = (float*)pProj;
    float* shid = (float*)pShid;  float* parts = (float*)pParts;
    float* s1 = (float*)pS1;      float* h1 = (float*)pH1;
    float* h2 = (float*)pH2;

    const int TOT = LL * CS;

    // 1: merged pack/prep + bias GEMM (2048 CTAs cover both works)
    prep_bias<<<2048, 256>>>(z, Wb, Wq, Wk, Wv, Wqp, Wkp, Wvp, quat, trsl, scale);
    // 2: projections (no split-K, direct write)
    gemm128<<<dim3(PW/64, LL/128, 1), 256>>>(s, Wcat, proj, CS, PW, PW, CS, CS, 0);
    // 3
    transform<<<LL, 384>>>();
    // 4: attn  <- profiled launch
    attn<<<LL, 256>>>();
    // 5
    op_gemm<<<LL, 256>>>(z);
    // 6: shid @ Ws, split-K=6
    gemm128<<<dim3(CS/64, LL/128, 6), 256>>>(shid, Ws, parts, SH, CS, CS, SH/6, SH, TOT);
    ln_combine<<<LL, 128>>>(parts, 6, TOT, bs, s, g1, b1, s1);
    gemm128<<<dim3(CS/64, LL/128, 6), 256>>>(s1, Wm1, parts, CS, CS, CS, CS/6, CS, TOT);
    combine<<<(TOT+255)/256, 256>>>(parts, 6, TOT, bm1, h1, TOT, CS, 1);
    gemm128<<<dim3(CS/64, LL/128, 6), 256>>>(h1, Wm2, parts, CS, CS, CS, CS/6, CS, TOT);
    combine<<<(TOT+255)/256, 256>>>(parts, 6, TOT, bm2, h2, TOT, CS, 1);
    gemm128<<<dim3(CS/64, LL/128, 6), 256>>>(h2, Wm3, parts, CS, CS, CS, CS/6, CS, TOT);
    ln_combine<<<LL, 128>>>(parts, 6, TOT, bm3, s1, g2, b2, out);
}

// round 13
// speedup vs baseline: 1.0431x; 1.0431x over previous
#include <cuda_runtime.h>
#include <math.h>

#define LL 512
#define CS 384
#define CZ 256
#define PW 1152
#define SH 3648
#define WLL 0.57735026918962576f
#define WCC 0.23570226039551584f

typedef unsigned long long u64;
__device__ __forceinline__ u64 dup2(float a){ u64 r; asm("mov.b64 %0,{%1,%1};" : "=l"(r) : "f"(a)); return r; }
__device__ __forceinline__ u64 pack2(float lo, float hi){ u64 r; asm("mov.b64 %0,{%1,%2};" : "=l"(r) : "f"(lo), "f"(hi)); return r; }
__device__ __forceinline__ void unpack2(u64 v, float& lo, float& hi){ asm("mov.b64 {%0,%1},%2;" : "=f"(lo), "=f"(hi) : "l"(v)); }
__device__ __forceinline__ void ffma2(u64& d, u64 a, u64 b){ asm("fma.rn.f32x2 %0,%1,%2,%0;" : "+l"(d) : "l"(a), "l"(b)); }

__device__ float g_Wcat[CS * PW];
__device__ float g_proj[LL * PW];   // [q 0|k 192|v 384|qp 576|kp 720|vp 864]
__device__ float g_R[LL * 9];
__device__ float g_t[LL * 3];
__device__ float g_coef[12];
__device__ float g_qpp[LL * 144];
__device__ float g_kT[192 * LL];
__device__ float g_vT[192 * LL];
__device__ float g_kppT[144 * LL];
__device__ float g_vppT[288 * LL];
__device__ float g_Bt[12 * LL * LL];    // bias logits, head-major [h][i*512+j]
__device__ float g_A[LL * 12 * LL];     // softmaxed attention [i][h][j]
__device__ float g_shid[LL * SH];
__device__ float g_parts[6 * LL * CS];
__device__ float g_s1[LL * CS];
__device__ float g_h1[LL * CS];
__device__ float g_h2[LL * CS];

// merged: weight packing + quat prep + bias GEMM (128 rows per CTA, 2048 CTAs)
__global__ __launch_bounds__(256) void prep_bias(
    const float* __restrict__ z, const float* __restrict__ Wb,
    const float* __restrict__ Wq, const float* __restrict__ Wk,
    const float* __restrict__ Wv, const float* __restrict__ Wqp,
    const float* __restrict__ Wkp, const float* __restrict__ Wvp,
    const float* __restrict__ quat, const float* __restrict__ trsl,
    const float* __restrict__ scale)
{
    int tid = threadIdx.x;
    int gid = blockIdx.x * 256 + tid;

    if (gid < CS * PW) {
        int r = gid / PW, c = gid - r * PW;
        float v;
        if      (c < 192)  v = Wq [r*192 + c];
        else if (c < 384)  v = Wk [r*192 + c-192];
        else if (c < 576)  v = Wv [r*192 + c-384];
        else if (c < 720)  v = Wqp[r*144 + c-576];
        else if (c < 864)  v = Wkp[r*144 + c-720];
        else               v = Wvp[r*288 + c-864];
        g_Wcat[gid] = v;
    }
    if (gid < LL) {
        float w = quat[gid*4], x = quat[gid*4+1], y = quat[gid*4+2], zz = quat[gid*4+3];
        float inv = rsqrtf(w*w + x*x + y*y + zz*zz);
        w *= inv; x *= inv; y *= inv; zz *= inv;
        float* R = g_R + gid*9;
        R[0]=1.f-2.f*(y*y+zz*zz); R[1]=2.f*(x*y-w*zz);     R[2]=2.f*(x*zz+w*y);
        R[3]=2.f*(x*y+w*zz);      R[4]=1.f-2.f*(x*x+zz*zz); R[5]=2.f*(y*zz-w*x);
        R[6]=2.f*(x*zz-w*y);      R[7]=2.f*(y*zz+w*x);      R[8]=1.f-2.f*(x*x+y*y);
        g_t[gid*3]=trsl[gid*3]; g_t[gid*3+1]=trsl[gid*3+1]; g_t[gid*3+2]=trsl[gid*3+2];
    }
    if (gid < 12) g_coef[gid] = 0.5f * WCC * log1pf(expf(scale[gid]));

    __shared__ u64 sW[CZ * 6];          // 12 KB
    __shared__ float sAz[128][33];      // 16.9 KB
    int row0 = blockIdx.x * 128;
    int q = tid & 127, hp = tid >> 7;

    for (int x = tid; x < CZ*6; x += 256) {
        int c = x / 6, p = x - c*6;
        sW[x] = pack2(Wb[c*12 + 2*p], Wb[c*12 + 2*p + 1]);
    }

    u64 acc[3] = {};
    for (int ch = 0; ch < 8; ch++) {
        __syncthreads();
        #pragma unroll
        for (int t0 = 0; t0 < 4; t0++) {
            int idx = tid + t0 * 256;
            int row = idx >> 3, c4 = idx & 7;
            float4 v = *(const float4*)(z + (size_t)(row0 + row) * CZ + ch*32 + c4*4);
            sAz[row][c4*4+0] = v.x; sAz[row][c4*4+1] = v.y;
            sAz[row][c4*4+2] = v.z; sAz[row][c4*4+3] = v.w;
        }
        __syncthreads();
        #pragma unroll 4
        for (int c = 0; c < 32; c++) {
            int cc = ch*32 + c;
            u64 d0 = dup2(sAz[q][c]);
            ffma2(acc[0], d0, sW[cc*6 + hp*3 + 0]);
            ffma2(acc[1], d0, sW[cc*6 + hp*3 + 1]);
            ffma2(acc[2], d0, sW[cc*6 + hp*3 + 2]);
        }
    }
    #pragma unroll
    for (int p = 0; p < 3; p++) {
        float lo, hi;
        unpack2(acc[p], lo, hi);
        g_Bt[(size_t)(hp*6+2*p  )*(LL*LL) + row0 + q] = lo;
        g_Bt[(size_t)(hp*6+2*p+1)*(LL*LL) + row0 + q] = hi;
    }
}

__global__ void transform()
{
    int i = blockIdx.x, pt = threadIdx.x;   // 384 threads
    if (pt < 192) g_kT[pt * LL + i] = g_proj[(size_t)i*PW + 192 + pt];
    else          g_vT[(pt-192) * LL + i] = g_proj[(size_t)i*PW + 384 + (pt-192)];
    if (pt >= 192) return;
    const float* R = g_R + i*9;
    const float* t = g_t + i*3;
    const float* src;
    if (pt < 48)      src = g_proj + (size_t)i*PW + 576 + pt*3;
    else if (pt < 96) src = g_proj + (size_t)i*PW + 720 + (pt-48)*3;
    else              src = g_proj + (size_t)i*PW + 864 + (pt-96)*3;
    float px = src[0], py = src[1], pz = src[2];
    float ox = R[0]*px + R[1]*py + R[2]*pz + t[0];
    float oy = R[3]*px + R[4]*py + R[5]*pz + t[1];
    float oz = R[6]*px + R[7]*py + R[8]*pz + t[2];
    if (pt < 48) {
        float* d = g_qpp + i*144 + pt*3;
        d[0] = ox; d[1] = oy; d[2] = oz;
    } else if (pt < 96) {
        int p = pt - 48;
        g_kppT[(p*3+0)*LL + i] = ox;
        g_kppT[(p*3+1)*LL + i] = oy;
        g_kppT[(p*3+2)*LL + i] = oz;
    } else {
        int p = pt - 96;
        g_vppT[(p*3+0)*LL + i] = ox;
        g_vppT[(p*3+1)*LL + i] = oy;
        g_vppT[(p*3+2)*LL + i] = oz;
    }
}

// 128x64 tile GEMM, 256 threads, 8x4/thread, A pre-duplicated f32x2 in smem
__global__ __launch_bounds__(256) void gemm128(const float* __restrict__ A,
                                               const float* __restrict__ B,
                                               float* __restrict__ C,
                                               int lda, int ldb, int ldc,
                                               int kSlice, int K, int partStride)
{
    __shared__ u64 As[16][128];
    __shared__ float Bs[16][64];
    int n0 = blockIdx.x * 64, m0 = blockIdx.y * 128;
    int k0 = blockIdx.z * kSlice;
    int kend = min(K, k0 + kSlice);
    float* Cc = C + (size_t)blockIdx.z * partStride;
    int tid = threadIdx.x;
    int tx = tid & 15, ty = tid >> 4;
    u64 acc[8][2] = {};
    for (int kt = k0; kt < kend; kt += 16) {
        #pragma unroll
        for (int half = 0; half < 2; half++) {
            int f = tid + half * 256;
            int row = f >> 2, kq = (f & 3) << 2;
            float4 av = *(const float4*)(A + (size_t)(m0 + row) * lda + kt + kq);
            As[kq+0][row] = dup2(av.x);
            As[kq+1][row] = dup2(av.y);
            As[kq+2][row] = dup2(av.z);
            As[kq+3][row] = dup2(av.w);
        }
        {
            int k = tid >> 4, nq = (tid & 15) << 2;
            *(float4*)&Bs[k][nq] = *(const float4*)(B + (size_t)(kt + k) * ldb + n0 + nq);
        }
        __syncthreads();
        #pragma unroll
        for (int kk = 0; kk < 16; kk++) {
            u64 a[8];
            *(ulonglong2*)&a[0] = *(ulonglong2*)&As[kk][ty*8+0];
            *(ulonglong2*)&a[2] = *(ulonglong2*)&As[kk][ty*8+2];
            *(ulonglong2*)&a[4] = *(ulonglong2*)&As[kk][ty*8+4];
            *(ulonglong2*)&a[6] = *(ulonglong2*)&As[kk][ty*8+6];
            ulonglong2 b2 = *(ulonglong2*)&Bs[kk][tx << 2];
            #pragma unroll
            for (int m = 0; m < 8; m++) {
                ffma2(acc[m][0], a[m], b2.x);
                ffma2(acc[m][1], a[m], b2.y);
            }
        }
        __syncthreads();
    }
    #pragma unroll
    for (int m = 0; m < 8; m++) {
        ulonglong2 st; st.x = acc[m][0]; st.y = acc[m][1];
        *(ulonglong2*)(Cc + (size_t)(m0 + ty*8 + m) * ldc + n0 + (tx << 2)) = st;
    }
}

__global__ void combine(const float* __restrict__ parts, int nparts, int partStride,
                        const float* __restrict__ bias, float* __restrict__ out,
                        int total, int N, int relu)
{
    int idx = blockIdx.x * blockDim.x + threadIdx.x;
    if (idx >= total) return;
    float v = parts[idx];
    for (int p = 1; p < nparts; p++) v += parts[(size_t)p * partStride + idx];
    if (bias) v += bias[idx % N];
    if (relu) v = fmaxf(v, 0.f);
    out[idx] = v;
}

__global__ void ln_combine(const float* __restrict__ parts, int nparts, int partStride,
                           const float* __restrict__ bias, const float* __restrict__ resid,
                           const float* __restrict__ gg, const float* __restrict__ bb,
                           float* __restrict__ out)
{
    int i = blockIdx.x, t = threadIdx.x;   // 128 threads
    float v[3];
    #pragma unroll
    for (int k = 0; k < 3; k++) {
        int c = t + k * 128;
        size_t off = (size_t)i * CS + c;
        float x = parts[off];
        for (int p = 1; p < nparts; p++) x += parts[(size_t)p * partStride + off];
        v[k] = x + bias[c] + resid[off];
    }
    float s = v[0]+v[1]+v[2], q = v[0]*v[0]+v[1]*v[1]+v[2]*v[2];
    #pragma unroll
    for (int o = 16; o; o >>= 1) {
        s += __shfl_xor_sync(0xffffffffu, s, o);
        q += __shfl_xor_sync(0xffffffffu, q, o);
    }
    __shared__ float ss[4], sq[4];
    int w = t >> 5, lane = t & 31;
    if (lane == 0) { ss[w] = s; sq[w] = q; }
    __syncthreads();
    if (t == 0) {
        float S = ss[0]+ss[1]+ss[2]+ss[3], Q = sq[0]+sq[1]+sq[2]+sq[3];
        float m = S * (1.f/CS);
        ss[0] = m; sq[0] = rsqrtf(Q*(1.f/CS) - m*m + 1e-5f);
    }
    __syncthreads();
    float m = ss[0], r = sq[0];
    float* o = out + (size_t)i * CS;
    #pragma unroll
    for (int k = 0; k < 3; k++) {
        int c = t + k * 128;
        o[c] = (v[k]-m)*r*gg[c] + bb[c];
    }
}

// attention: logits + softmax + ov/ovp; writes weights to g_A
// head loop NOT unrolled -> bounded register pressure (was 255 regs, occ 12.5%)
__global__ __launch_bounds__(256) void attn()
{
    __shared__ float sA[12 * LL];     // 24 KB
    __shared__ float sq[192], sqpp[144], sR[9], st3[3], scoef[12], sOVP[288];

    int i = blockIdx.x, tid = threadIdx.x;
    int lane = tid & 31, w = tid >> 5;

    if (tid < 192) sq[tid] = g_proj[(size_t)i * PW + tid];
    if (tid < 144) sqpp[tid] = g_qpp[i*144 + tid];
    if (tid < 9)   sR[tid] = g_R[i*9 + tid];
    if (tid < 3)   st3[tid] = g_t[i*3 + tid];
    if (tid < 12)  scoef[tid] = g_coef[tid];
    __syncthreads();

    // ---- logits: rows j=tid, j=tid+256; heads serialized (reg pressure) ----
    #pragma unroll 1
    for (int h = 0; h < 12; h++) {
        float qk0 = 0.f, qk1 = 0.f;
        const float* kTb = g_kT + (size_t)(h*16)*LL + tid;
        #pragma unroll
        for (int d = 0; d < 16; d++) {
            float qv = sq[h*16+d];
            qk0 = fmaf(qv, kTb[d*LL], qk0);
            qk1 = fmaf(qv, kTb[d*LL + 256], qk1);
        }
        float d20 = 0.f, d21 = 0.f;
        const float* kpb = g_kppT + (size_t)(h*12)*LL + tid;
        #pragma unroll
        for (int e = 0; e < 12; e++) {
            float qp = sqpp[h*12+e];
            float dd0 = qp - kpb[e*LL];
            float dd1 = qp - kpb[e*LL + 256];
            d20 = fmaf(dd0, dd0, d20);
            d21 = fmaf(dd1, dd1, d21);
        }
        const float* bp = g_Bt + (size_t)h * (LL*LL) + (size_t)i * LL + tid;
        float cf = scoef[h];
        sA[h*LL + tid]       = WLL * (qk0 * 0.25f + bp[0]   - cf * d20);
        sA[h*LL + tid + 256] = WLL * (qk1 * 0.25f + bp[256] - cf * d21);
    }
    __syncthreads();

    for (int h = w; h < 12; h += 8) {
        float* row = sA + h * LL;
        float m = -1e30f;
        for (int j = lane; j < LL; j += 32) m = fmaxf(m, row[j]);
        #pragma unroll
        for (int o = 16; o; o >>= 1) m = fmaxf(m, __shfl_xor_sync(0xffffffffu, m, o));
        float sum = 0.f;
        for (int j = lane; j < LL; j += 32) {
            float e = __expf(row[j] - m);
            row[j] = e; sum += e;
        }
        #pragma unroll
        for (int o = 16; o; o >>= 1) sum += __shfl_xor_sync(0xffffffffu, sum, o);
        float inv = 1.f / sum;
        for (int j = lane; j < LL; j += 32) row[j] *= inv;
    }
    __syncthreads();

    {
        float* ga = g_A + (size_t)i * 12 * LL;
        for (int x = tid * 4; x < 12 * LL; x += 1024)
            *(float4*)(ga + x) = *(const float4*)&sA[x];
    }

    if (tid < 240) {
        int h = tid / 20, o = (tid % 20) * 2;
        const float* s0;
        if (o < 16) s0 = g_vT + (h*16+o)*LL;
        else        s0 = g_vppT + (h*24+o-16)*LL;
        const float* s1p = s0 + LL;
        const float* ap = sA + h * LL;
        float a0 = 0.f, a1 = 0.f;
        for (int j = 0; j < LL; j += 8) {
            float4 v0a = *(const float4*)(s0 + j),  v0b = *(const float4*)(s0 + j + 4);
            float4 v1a = *(const float4*)(s1p + j), v1b = *(const float4*)(s1p + j + 4);
            float4 aa  = *(const float4*)(ap + j),  ab  = *(const float4*)(ap + j + 4);
            a0 = fmaf(aa.x,v0a.x,fmaf(aa.y,v0a.y,fmaf(aa.z,v0a.z,fmaf(aa.w,v0a.w,a0))));
            a0 = fmaf(ab.x,v0b.x,fmaf(ab.y,v0b.y,fmaf(ab.z,v0b.z,fmaf(ab.w,v0b.w,a0))));
            a1 = fmaf(aa.x,v1a.x,fmaf(aa.y,v1a.y,fmaf(aa.z,v1a.z,fmaf(aa.w,v1a.w,a1))));
            a1 = fmaf(ab.x,v1b.x,fmaf(ab.y,v1b.y,fmaf(ab.z,v1b.z,fmaf(ab.w,v1b.w,a1))));
        }
        float* orow = g_shid + (size_t)i * SH + h * 304;
        if (o < 16) { orow[256+o] = a0; orow[257+o] = a1; }
        else        { sOVP[h*24 + o-16] = a0; sOVP[h*24 + o-15] = a1; }
    }
    __syncthreads();

    if (tid < 96) {
        int h = tid >> 3, vv = tid & 7;
        float gx = sOVP[h*24 + vv*3 + 0] - st3[0];
        float gy = sOVP[h*24 + vv*3 + 1] - st3[1];
        float gz = sOVP[h*24 + vv*3 + 2] - st3[2];
        float lx = sR[0]*gx + sR[3]*gy + sR[6]*gz;
        float ly = sR[1]*gx + sR[4]*gy + sR[7]*gz;
        float lz = sR[2]*gx + sR[5]*gy + sR[8]*gz;
        float* orow = g_shid + (size_t)i * SH + h * 304;
        orow[272 + vv*3 + 0] = lx;
        orow[272 + vv*3 + 1] = ly;
        orow[272 + vv*3 + 2] = lz;
        orow[296 + vv] = sqrtf(lx*lx + ly*ly + lz*lz);
    }
}

// op = a^T @ z per query row, packed f32x2; one CTA per i
__global__ __launch_bounds__(256) void op_gemm(const float* __restrict__ z)
{
    __shared__ float sA[12 * LL];   // 24 KB
    int i = blockIdx.x, tid = threadIdx.x;
    const float* ga = g_A + (size_t)i * 12 * LL;
    for (int x = tid * 4; x < 12 * LL; x += 1024)
        *(float4*)&sA[x] = *(const float4*)(ga + x);
    __syncthreads();

    int h0 = (tid >> 6) * 3;
    int cc = (tid & 63) << 2;
    const float* zp = z + (size_t)i * LL * CZ + cc;
    const float* a0p = sA + (h0+0) * LL;
    const float* a1p = sA + (h0+1) * LL;
    const float* a2p = sA + (h0+2) * LL;
    u64 acc[3][2] = {};
    for (int j = 0; j < LL; j += 4) {
        ulonglong2 zv[4];
        #pragma unroll
        for (int u = 0; u < 4; u++)
            zv[u] = *(const ulonglong2*)(zp + (size_t)(j+u) * CZ);
        float4 a0 = *(const float4*)(a0p + j);
        float4 a1 = *(const float4*)(a1p + j);
        float4 a2 = *(const float4*)(a2p + j);
        float a0v[4] = {a0.x,a0.y,a0.z,a0.w};
        float a1v[4] = {a1.x,a1.y,a1.z,a1.w};
        float a2v[4] = {a2.x,a2.y,a2.z,a2.w};
        #pragma unroll
        for (int u = 0; u < 4; u++) {
            u64 d0 = dup2(a0v[u]), d1 = dup2(a1v[u]), d2 = dup2(a2v[u]);
            ffma2(acc[0][0], zv[u].x, d0); ffma2(acc[0][1], zv[u].y, d0);
            ffma2(acc[1][0], zv[u].x, d1); ffma2(acc[1][1], zv[u].y, d1);
            ffma2(acc[2][0], zv[u].x, d2); ffma2(acc[2][1], zv[u].y, d2);
        }
    }
    float* orow = g_shid + (size_t)i * SH;
    #pragma unroll
    for (int hh = 0; hh < 3; hh++) {
        ulonglong2 st; st.x = acc[hh][0]; st.y = acc[hh][1];
        *(ulonglong2*)(orow + (h0+hh)*304 + cc) = st;
    }
}

extern "C" void kernel_launch(void* const* d_in, const int* in_sizes, int n_in,
                              void* d_out, int out_size)
{
    const float* s    = (const float*)d_in[0];
    const float* z    = (const float*)d_in[1];
    const float* quat = (const float*)d_in[2];
    const float* trsl = (const float*)d_in[3];
    const float* Wq   = (const float*)d_in[4];
    const float* Wk   = (const float*)d_in[5];
    const float* Wv   = (const float*)d_in[6];
    const float* Wqp  = (const float*)d_in[7];
    const float* Wkp  = (const float*)d_in[8];
    const float* Wvp  = (const float*)d_in[9];
    const float* Wb   = (const float*)d_in[10];
    const float* Ws   = (const float*)d_in[11];
    const float* bs   = (const float*)d_in[12];
    const float* scale= (const float*)d_in[13];
    const float* g1   = (const float*)d_in[14];
    const float* b1   = (const float*)d_in[15];
    const float* Wm1  = (const float*)d_in[16];
    const float* bm1  = (const float*)d_in[17];
    const float* Wm2  = (const float*)d_in[18];
    const float* bm2  = (const float*)d_in[19];
    const float* Wm3  = (const float*)d_in[20];
    const float* bm3  = (const float*)d_in[21];
    const float* g2   = (const float*)d_in[22];
    const float* b2   = (const float*)d_in[23];
    float* out = (float*)d_out;

    void *pWcat, *pProj, *pShid, *pParts, *pS1, *pH1, *pH2;
    cudaGetSymbolAddress(&pWcat,  g_Wcat);
    cudaGetSymbolAddress(&pProj,  g_proj);
    cudaGetSymbolAddress(&pShid,  g_shid);
    cudaGetSymbolAddress(&pParts, g_parts);
    cudaGetSymbolAddress(&pS1,    g_s1);
    cudaGetSymbolAddress(&pH1,    g_h1);
    cudaGetSymbolAddress(&pH2,    g_h2);
    float* Wcat = (float*)pWcat;  float* proj = (float*)pProj;
    float* shid = (float*)pShid;  float* parts = (float*)pParts;
    float* s1 = (float*)pS1;      float* h1 = (float*)pH1;
    float* h2 = (float*)pH2;

    const int TOT = LL * CS;

    prep_bias<<<2048, 256>>>(z, Wb, Wq, Wk, Wv, Wqp, Wkp, Wvp, quat, trsl, scale);
    gemm128<<<dim3(PW/64, LL/128, 1), 256>>>(s, Wcat, proj, CS, PW, PW, CS, CS, 0);
    transform<<<LL, 384>>>();
    // 4: attn  <- profiled launch; verify regs/occ prediction
    attn<<<LL, 256>>>();
    op_gemm<<<LL, 256>>>(z);
    gemm128<<<dim3(CS/64, LL/128, 6), 256>>>(shid, Ws, parts, SH, CS, CS, SH/6, SH, TOT);
    ln_combine<<<LL, 128>>>(parts, 6, TOT, bs, s, g1, b1, s1);
    gemm128<<<dim3(CS/64, LL/128, 6), 256>>>(s1, Wm1, parts, CS, CS, CS, CS/6, CS, TOT);
    combine<<<(TOT+255)/256, 256>>>(parts, 6, TOT, bm1, h1, TOT, CS, 1);
    gemm128<<<dim3(CS/64, LL/128, 6), 256>>>(h1, Wm2, parts, CS, CS, CS, CS/6, CS, TOT);
    combine<<<(TOT+255)/256, 256>>>(parts, 6, TOT, bm2, h2, TOT, CS, 1);
    gemm128<<<dim3(CS/64, LL/128, 6), 256>>>(h2, Wm3, parts, CS, CS, CS, CS/6, CS, TOT);
    ln_combine<<<LL, 128>>>(parts, 6, TOT, bm3, s1, g2, b2, out);
}

// round 15
// speedup vs baseline: 1.1931x; 1.1438x over previous
#include <cuda_runtime.h>
#include <math.h>

#define LL 512
#define CS 384
#define CZ 256
#define PW 1152
#define SH 3648
#define WLL 0.57735026918962576f
#define WCC 0.23570226039551584f

typedef unsigned long long u64;
__device__ __forceinline__ u64 dup2(float a){ u64 r; asm("mov.b64 %0,{%1,%1};" : "=l"(r) : "f"(a)); return r; }
__device__ __forceinline__ u64 pack2(float lo, float hi){ u64 r; asm("mov.b64 %0,{%1,%2};" : "=l"(r) : "f"(lo), "f"(hi)); return r; }
__device__ __forceinline__ void unpack2(u64 v, float& lo, float& hi){ asm("mov.b64 {%0,%1},%2;" : "=f"(lo), "=f"(hi) : "l"(v)); }
__device__ __forceinline__ void ffma2(u64& d, u64 a, u64 b){ asm("fma.rn.f32x2 %0,%1,%2,%0;" : "+l"(d) : "l"(a), "l"(b)); }

__device__ float g_Wcat[CS * PW];
__device__ float g_proj[LL * PW];   // [q 0|k 192|v 384|qp 576|kp 720|vp 864]
__device__ float g_R[LL * 9];
__device__ float g_t[LL * 3];
__device__ float g_coef[12];
__device__ float g_qpp[LL * 144];
__device__ float g_kT[192 * LL];
__device__ float g_vT[192 * LL];
__device__ float g_kppT[144 * LL];
__device__ float g_vppT[288 * LL];
__device__ float g_Bt[12 * LL * LL];    // bias logits, head-major [h][i*512+j]
__device__ float g_A[LL * 12 * LL];     // softmaxed attention [i][h][j]
__device__ float g_shid[LL * SH];
__device__ float g_parts[6 * LL * CS];
__device__ float g_s1[LL * CS];
__device__ float g_h1[LL * CS];
__device__ float g_h2[LL * CS];

// merged: weight packing + quat prep + bias GEMM (128 rows per CTA, 2048 CTAs)
__global__ __launch_bounds__(256) void prep_bias(
    const float* __restrict__ z, const float* __restrict__ Wb,
    const float* __restrict__ Wq, const float* __restrict__ Wk,
    const float* __restrict__ Wv, const float* __restrict__ Wqp,
    const float* __restrict__ Wkp, const float* __restrict__ Wvp,
    const float* __restrict__ quat, const float* __restrict__ trsl,
    const float* __restrict__ scale)
{
    int tid = threadIdx.x;
    int gid = blockIdx.x * 256 + tid;

    if (gid < CS * PW) {
        int r = gid / PW, c = gid - r * PW;
        float v;
        if      (c < 192)  v = Wq [r*192 + c];
        else if (c < 384)  v = Wk [r*192 + c-192];
        else if (c < 576)  v = Wv [r*192 + c-384];
        else if (c < 720)  v = Wqp[r*144 + c-576];
        else if (c < 864)  v = Wkp[r*144 + c-720];
        else               v = Wvp[r*288 + c-864];
        g_Wcat[gid] = v;
    }
    if (gid < LL) {
        float w = quat[gid*4], x = quat[gid*4+1], y = quat[gid*4+2], zz = quat[gid*4+3];
        float inv = rsqrtf(w*w + x*x + y*y + zz*zz);
        w *= inv; x *= inv; y *= inv; zz *= inv;
        float* R = g_R + gid*9;
        R[0]=1.f-2.f*(y*y+zz*zz); R[1]=2.f*(x*y-w*zz);     R[2]=2.f*(x*zz+w*y);
        R[3]=2.f*(x*y+w*zz);      R[4]=1.f-2.f*(x*x+zz*zz); R[5]=2.f*(y*zz-w*x);
        R[6]=2.f*(x*zz-w*y);      R[7]=2.f*(y*zz+w*x);      R[8]=1.f-2.f*(x*x+y*y);
        g_t[gid*3]=trsl[gid*3]; g_t[gid*3+1]=trsl[gid*3+1]; g_t[gid*3+2]=trsl[gid*3+2];
    }
    if (gid < 12) g_coef[gid] = 0.5f * WCC * log1pf(expf(scale[gid]));

    __shared__ u64 sW[CZ * 6];          // 12 KB
    __shared__ float sAz[128][33];      // 16.9 KB
    int row0 = blockIdx.x * 128;
    int q = tid & 127, hp = tid >> 7;

    for (int x = tid; x < CZ*6; x += 256) {
        int c = x / 6, p = x - c*6;
        sW[x] = pack2(Wb[c*12 + 2*p], Wb[c*12 + 2*p + 1]);
    }

    u64 acc[3] = {};
    for (int ch = 0; ch < 8; ch++) {
        __syncthreads();
        #pragma unroll
        for (int t0 = 0; t0 < 4; t0++) {
            int idx = tid + t0 * 256;
            int row = idx >> 3, c4 = idx & 7;
            float4 v = *(const float4*)(z + (size_t)(row0 + row) * CZ + ch*32 + c4*4);
            sAz[row][c4*4+0] = v.x; sAz[row][c4*4+1] = v.y;
            sAz[row][c4*4+2] = v.z; sAz[row][c4*4+3] = v.w;
        }
        __syncthreads();
        #pragma unroll 4
        for (int c = 0; c < 32; c++) {
            int cc = ch*32 + c;
            u64 d0 = dup2(sAz[q][c]);
            ffma2(acc[0], d0, sW[cc*6 + hp*3 + 0]);
            ffma2(acc[1], d0, sW[cc*6 + hp*3 + 1]);
            ffma2(acc[2], d0, sW[cc*6 + hp*3 + 2]);
        }
    }
    #pragma unroll
    for (int p = 0; p < 3; p++) {
        float lo, hi;
        unpack2(acc[p], lo, hi);
        g_Bt[(size_t)(hp*6+2*p  )*(LL*LL) + row0 + q] = lo;
        g_Bt[(size_t)(hp*6+2*p+1)*(LL*LL) + row0 + q] = hi;
    }
}

__global__ void transform()
{
    int i = blockIdx.x, pt = threadIdx.x;   // 384 threads
    if (pt < 192) g_kT[pt * LL + i] = g_proj[(size_t)i*PW + 192 + pt];
    else          g_vT[(pt-192) * LL + i] = g_proj[(size_t)i*PW + 384 + (pt-192)];
    if (pt >= 192) return;
    const float* R = g_R + i*9;
    const float* t = g_t + i*3;
    const float* src;
    if (pt < 48)      src = g_proj + (size_t)i*PW + 576 + pt*3;
    else if (pt < 96) src = g_proj + (size_t)i*PW + 720 + (pt-48)*3;
    else              src = g_proj + (size_t)i*PW + 864 + (pt-96)*3;
    float px = src[0], py = src[1], pz = src[2];
    float ox = R[0]*px + R[1]*py + R[2]*pz + t[0];
    float oy = R[3]*px + R[4]*py + R[5]*pz + t[1];
    float oz = R[6]*px + R[7]*py + R[8]*pz + t[2];
    if (pt < 48) {
        float* d = g_qpp + i*144 + pt*3;
        d[0] = ox; d[1] = oy; d[2] = oz;
    } else if (pt < 96) {
        int p = pt - 48;
        g_kppT[(p*3+0)*LL + i] = ox;
        g_kppT[(p*3+1)*LL + i] = oy;
        g_kppT[(p*3+2)*LL + i] = oz;
    } else {
        int p = pt - 96;
        g_vppT[(p*3+0)*LL + i] = ox;
        g_vppT[(p*3+1)*LL + i] = oy;
        g_vppT[(p*3+2)*LL + i] = oz;
    }
}

// 128x64 tile GEMM, 256 threads, 8x4/thread, A pre-duplicated f32x2 in smem
__global__ __launch_bounds__(256) void gemm128(const float* __restrict__ A,
                                               const float* __restrict__ B,
                                               float* __restrict__ C,
                                               int lda, int ldb, int ldc,
                                               int kSlice, int K, int partStride)
{
    __shared__ u64 As[16][128];
    __shared__ float Bs[16][64];
    int n0 = blockIdx.x * 64, m0 = blockIdx.y * 128;
    int k0 = blockIdx.z * kSlice;
    int kend = min(K, k0 + kSlice);
    float* Cc = C + (size_t)blockIdx.z * partStride;
    int tid = threadIdx.x;
    int tx = tid & 15, ty = tid >> 4;
    u64 acc[8][2] = {};
    for (int kt = k0; kt < kend; kt += 16) {
        #pragma unroll
        for (int half = 0; half < 2; half++) {
            int f = tid + half * 256;
            int row = f >> 2, kq = (f & 3) << 2;
            float4 av = *(const float4*)(A + (size_t)(m0 + row) * lda + kt + kq);
            As[kq+0][row] = dup2(av.x);
            As[kq+1][row] = dup2(av.y);
            As[kq+2][row] = dup2(av.z);
            As[kq+3][row] = dup2(av.w);
        }
        {
            int k = tid >> 4, nq = (tid & 15) << 2;
            *(float4*)&Bs[k][nq] = *(const float4*)(B + (size_t)(kt + k) * ldb + n0 + nq);
        }
        __syncthreads();
        #pragma unroll
        for (int kk = 0; kk < 16; kk++) {
            u64 a[8];
            *(ulonglong2*)&a[0] = *(ulonglong2*)&As[kk][ty*8+0];
            *(ulonglong2*)&a[2] = *(ulonglong2*)&As[kk][ty*8+2];
            *(ulonglong2*)&a[4] = *(ulonglong2*)&As[kk][ty*8+4];
            *(ulonglong2*)&a[6] = *(ulonglong2*)&As[kk][ty*8+6];
            ulonglong2 b2 = *(ulonglong2*)&Bs[kk][tx << 2];
            #pragma unroll
            for (int m = 0; m < 8; m++) {
                ffma2(acc[m][0], a[m], b2.x);
                ffma2(acc[m][1], a[m], b2.y);
            }
        }
        __syncthreads();
    }
    #pragma unroll
    for (int m = 0; m < 8; m++) {
        ulonglong2 st; st.x = acc[m][0]; st.y = acc[m][1];
        *(ulonglong2*)(Cc + (size_t)(m0 + ty*8 + m) * ldc + n0 + (tx << 2)) = st;
    }
}

__global__ void combine(const float* __restrict__ parts, int nparts, int partStride,
                        const float* __restrict__ bias, float* __restrict__ out,
                        int total, int N, int relu)
{
    int idx = blockIdx.x * blockDim.x + threadIdx.x;
    if (idx >= total) return;
    float v = parts[idx];
    for (int p = 1; p < nparts; p++) v += parts[(size_t)p * partStride + idx];
    if (bias) v += bias[idx % N];
    if (relu) v = fmaxf(v, 0.f);
    out[idx] = v;
}

__global__ void ln_combine(const float* __restrict__ parts, int nparts, int partStride,
                           const float* __restrict__ bias, const float* __restrict__ resid,
                           const float* __restrict__ gg, const float* __restrict__ bb,
                           float* __restrict__ out)
{
    int i = blockIdx.x, t = threadIdx.x;   // 128 threads
    float v[3];
    #pragma unroll
    for (int k = 0; k < 3; k++) {
        int c = t + k * 128;
        size_t off = (size_t)i * CS + c;
        float x = parts[off];
        for (int p = 1; p < nparts; p++) x += parts[(size_t)p * partStride + off];
        v[k] = x + bias[c] + resid[off];
    }
    float s = v[0]+v[1]+v[2], q = v[0]*v[0]+v[1]*v[1]+v[2]*v[2];
    #pragma unroll
    for (int o = 16; o; o >>= 1) {
        s += __shfl_xor_sync(0xffffffffu, s, o);
        q += __shfl_xor_sync(0xffffffffu, q, o);
    }
    __shared__ float ss[4], sq[4];
    int w = t >> 5, lane = t & 31;
    if (lane == 0) { ss[w] = s; sq[w] = q; }
    __syncthreads();
    if (t == 0) {
        float S = ss[0]+ss[1]+ss[2]+ss[3], Q = sq[0]+sq[1]+sq[2]+sq[3];
        float m = S * (1.f/CS);
        ss[0] = m; sq[0] = rsqrtf(Q*(1.f/CS) - m*m + 1e-5f);
    }
    __syncthreads();
    float m = ss[0], r = sq[0];
    float* o = out + (size_t)i * CS;
    #pragma unroll
    for (int k = 0; k < 3; k++) {
        int c = t + k * 128;
        o[c] = (v[k]-m)*r*gg[c] + bb[c];
    }
}

// attention: logits + softmax + ov/ovp; 512 threads (1 row/thread),
// ov/ovp warp-cooperative (coalesced over j)
__global__ __launch_bounds__(512) void attn()
{
    __shared__ float sA[12 * LL];     // 24 KB
    __shared__ float sq[192], sqpp[144], sR[9], st3[3], scoef[12], sOVP[288];

    int i = blockIdx.x, tid = threadIdx.x;
    int lane = tid & 31, w = tid >> 5;     // 16 warps

    if (tid < 192) sq[tid] = g_proj[(size_t)i * PW + tid];
    if (tid < 144) sqpp[tid] = g_qpp[i*144 + tid];
    if (tid < 9)   sR[tid] = g_R[i*9 + tid];
    if (tid < 3)   st3[tid] = g_t[i*3 + tid];
    if (tid < 12)  scoef[tid] = g_coef[tid];
    __syncthreads();

    // ---- logits: one row j=tid per thread; heads serialized ----
    #pragma unroll 1
    for (int h = 0; h < 12; h++) {
        float qk0 = 0.f;
        const float* kTb = g_kT + (size_t)(h*16)*LL + tid;
        #pragma unroll
        for (int d = 0; d < 16; d++)
            qk0 = fmaf(sq[h*16+d], kTb[d*LL], qk0);
        float d20 = 0.f;
        const float* kpb = g_kppT + (size_t)(h*12)*LL + tid;
        #pragma unroll
        for (int e = 0; e < 12; e++) {
            float dd0 = sqpp[h*12+e] - kpb[e*LL];
            d20 = fmaf(dd0, dd0, d20);
        }
        float bh = g_Bt[(size_t)h * (LL*LL) + (size_t)i * LL + tid];
        sA[h*LL + tid] = WLL * (qk0 * 0.25f + bh - scoef[h] * d20);
    }
    __syncthreads();

    // ---- softmax per head: warp w handles head w (12 of 16 warps) ----
    if (w < 12) {
        float* row = sA + w * LL;
        float m = -1e30f;
        for (int j = lane; j < LL; j += 32) m = fmaxf(m, row[j]);
        #pragma unroll
        for (int o = 16; o; o >>= 1) m = fmaxf(m, __shfl_xor_sync(0xffffffffu, m, o));
        float sum = 0.f;
        for (int j = lane; j < LL; j += 32) {
            float e = __expf(row[j] - m);
            row[j] = e; sum += e;
        }
        #pragma unroll
        for (int o = 16; o; o >>= 1) sum += __shfl_xor_sync(0xffffffffu, sum, o);
        float inv = 1.f / sum;
        for (int j = lane; j < LL; j += 32) row[j] *= inv;
    }
    __syncthreads();

    // ---- export weights for op_gemm ----
    {
        float* ga = g_A + (size_t)i * 12 * LL;
        for (int x = tid * 4; x < 12 * LL; x += 2048)
            *(float4*)(ga + x) = *(const float4*)&sA[x];
    }

    // ---- ov (16 dims) + ovp_g (24 dims): warp-cooperative, coalesced over j ----
    for (int task = w; task < 480; task += 16) {
        int h = task / 40, dim = task % 40;
        const float* src = (dim < 16) ? g_vT + (size_t)(h*16+dim)*LL
                                      : g_vppT + (size_t)(h*24+dim-16)*LL;
        const float* ap = sA + h * LL;
        float acc = 0.f;
        #pragma unroll
        for (int it = 0; it < 4; it++) {
            int j = (lane + it*32) * 4;
            float4 vv = *(const float4*)(src + j);
            float4 aa = *(const float4*)(ap + j);
            acc = fmaf(aa.x,vv.x, fmaf(aa.y,vv.y, fmaf(aa.z,vv.z, fmaf(aa.w,vv.w, acc))));
        }
        #pragma unroll
        for (int o = 16; o; o >>= 1) acc += __shfl_xor_sync(0xffffffffu, acc, o);
        if (lane == 0) {
            float* orow = g_shid + (size_t)i * SH + h * 304;
            if (dim < 16) orow[256+dim] = acc;
            else          sOVP[h*24 + dim-16] = acc;
        }
    }
    __syncthreads();

    // ---- ovp = R^T (ovp_g - t), norms ----
    if (tid < 96) {
        int h = tid >> 3, vv = tid & 7;
        float gx = sOVP[h*24 + vv*3 + 0] - st3[0];
        float gy = sOVP[h*24 + vv*3 + 1] - st3[1];
        float gz = sOVP[h*24 + vv*3 + 2] - st3[2];
        float lx = sR[0]*gx + sR[3]*gy + sR[6]*gz;
        float ly = sR[1]*gx + sR[4]*gy + sR[7]*gz;
        float lz = sR[2]*gx + sR[5]*gy + sR[8]*gz;
        float* orow = g_shid + (size_t)i * SH + h * 304;
        orow[272 + vv*3 + 0] = lx;
        orow[272 + vv*3 + 1] = ly;
        orow[272 + vv*3 + 2] = lz;
        orow[296 + vv] = sqrtf(lx*lx + ly*ly + lz*lz);
    }
}

// op = a^T @ z per query row, packed f32x2; one CTA per i
__global__ __launch_bounds__(256) void op_gemm(const float* __restrict__ z)
{
    __shared__ float sA[12 * LL];   // 24 KB
    int i = blockIdx.x, tid = threadIdx.x;
    const float* ga = g_A + (size_t)i * 12 * LL;
    for (int x = tid * 4; x < 12 * LL; x += 1024)
        *(float4*)&sA[x] = *(const float4*)(ga + x);
    __syncthreads();

    int h0 = (tid >> 6) * 3;
    int cc = (tid & 63) << 2;
    const float* zp = z + (size_t)i * LL * CZ + cc;
    const float* a0p = sA + (h0+0) * LL;
    const float* a1p = sA + (h0+1) * LL;
    const float* a2p = sA + (h0+2) * LL;
    u64 acc[3][2] = {};
    for (int j = 0; j < LL; j += 4) {
        ulonglong2 zv[4];
        #pragma unroll
        for (int u = 0; u < 4; u++)
            zv[u] = *(const ulonglong2*)(zp + (size_t)(j+u) * CZ);
        float4 a0 = *(const float4*)(a0p + j);
        float4 a1 = *(const float4*)(a1p + j);
        float4 a2 = *(const float4*)(a2p + j);
        float a0v[4] = {a0.x,a0.y,a0.z,a0.w};
        float a1v[4] = {a1.x,a1.y,a1.z,a1.w};
        float a2v[4] = {a2.x,a2.y,a2.z,a2.w};
        #pragma unroll
        for (int u = 0; u < 4; u++) {
            u64 d0 = dup2(a0v[u]), d1 = dup2(a1v[u]), d2 = dup2(a2v[u]);
            ffma2(acc[0][0], zv[u].x, d0); ffma2(acc[0][1], zv[u].y, d0);
            ffma2(acc[1][0], zv[u].x, d1); ffma2(acc[1][1], zv[u].y, d1);
            ffma2(acc[2][0], zv[u].x, d2); ffma2(acc[2][1], zv[u].y, d2);
        }
    }
    float* orow = g_shid + (size_t)i * SH;
    #pragma unroll
    for (int hh = 0; hh < 3; hh++) {
        ulonglong2 st; st.x = acc[hh][0]; st.y = acc[hh][1];
        *(ulonglong2*)(orow + (h0+hh)*304 + cc) = st;
    }
}

extern "C" void kernel_launch(void* const* d_in, const int* in_sizes, int n_in,
                              void* d_out, int out_size)
{
    const float* s    = (const float*)d_in[0];
    const float* z    = (const float*)d_in[1];
    const float* quat = (const float*)d_in[2];
    const float* trsl = (const float*)d_in[3];
    const float* Wq   = (const float*)d_in[4];
    const float* Wk   = (const float*)d_in[5];
    const float* Wv   = (const float*)d_in[6];
    const float* Wqp  = (const float*)d_in[7];
    const float* Wkp  = (const float*)d_in[8];
    const float* Wvp  = (const float*)d_in[9];
    const float* Wb   = (const float*)d_in[10];
    const float* Ws   = (const float*)d_in[11];
    const float* bs   = (const float*)d_in[12];
    const float* scale= (const float*)d_in[13];
    const float* g1   = (const float*)d_in[14];
    const float* b1   = (const float*)d_in[15];
    const float* Wm1  = (const float*)d_in[16];
    const float* bm1  = (const float*)d_in[17];
    const float* Wm2  = (const float*)d_in[18];
    const float* bm2  = (const float*)d_in[19];
    const float* Wm3  = (const float*)d_in[20];
    const float* bm3  = (const float*)d_in[21];
    const float* g2   = (const float*)d_in[22];
    const float* b2   = (const float*)d_in[23];
    float* out = (float*)d_out;

    void *pWcat, *pProj, *pShid, *pParts, *pS1, *pH1, *pH2;
    cudaGetSymbolAddress(&pWcat,  g_Wcat);
    cudaGetSymbolAddress(&pProj,  g_proj);
    cudaGetSymbolAddress(&pShid,  g_shid);
    cudaGetSymbolAddress(&pParts, g_parts);
    cudaGetSymbolAddress(&pS1,    g_s1);
    cudaGetSymbolAddress(&pH1,    g_h1);
    cudaGetSymbolAddress(&pH2,    g_h2);
    float* Wcat = (float*)pWcat;  float* proj = (float*)pProj;
    float* shid = (float*)pShid;  float* parts = (float*)pParts;
    float* s1 = (float*)pS1;      float* h1 = (float*)pH1;
    float* h2 = (float*)pH2;

    const int TOT = LL * CS;

    prep_bias<<<2048, 256>>>(z, Wb, Wq, Wk, Wv, Wqp, Wkp, Wvp, quat, trsl, scale);
    gemm128<<<dim3(PW/64, LL/128, 1), 256>>>(s, Wcat, proj, CS, PW, PW, CS, CS, 0);
    transform<<<LL, 384>>>();
    // 4: attn  <- profiled launch; verify L1/occ prediction
    attn<<<LL, 512>>>();
    op_gemm<<<LL, 256>>>(z);
    gemm128<<<dim3(CS/64, LL/128, 6), 256>>>(shid, Ws, parts, SH, CS, CS, SH/6, SH, TOT);
    ln_combine<<<LL, 128>>>(parts, 6, TOT, bs, s, g1, b1, s1);
    gemm128<<<dim3(CS/64, LL/128, 6), 256>>>(s1, Wm1, parts, CS, CS, CS, CS/6, CS, TOT);
    combine<<<(TOT+255)/256, 256>>>(parts, 6, TOT, bm1, h1, TOT, CS, 1);
    gemm128<<<dim3(CS/64, LL/128, 6), 256>>>(h1, Wm2, parts, CS, CS, CS, CS/6, CS, TOT);
    combine<<<(TOT+255)/256, 256>>>(parts, 6, TOT, bm2, h2, TOT, CS, 1);
    gemm128<<<dim3(CS/64, LL/128, 6), 256>>>(h2, Wm3, parts, CS, CS, CS, CS/6, CS, TOT);
    ln_combine<<<LL, 128>>>(parts, 6, TOT, bm3, s1, g2, b2, out);
}

// round 16
// speedup vs baseline: 1.3120x; 1.0997x over previous
#include <cuda_runtime.h>
#include <math.h>

#define LL 512
#define CS 384
#define CZ 256
#define PW 1152
#define SH 3648
#define WLL 0.57735026918962576f
#define WCC 0.23570226039551584f

typedef unsigned long long u64;
__device__ __forceinline__ u64 dup2(float a){ u64 r; asm("mov.b64 %0,{%1,%1};" : "=l"(r) : "f"(a)); return r; }
__device__ __forceinline__ u64 pack2(float lo, float hi){ u64 r; asm("mov.b64 %0,{%1,%2};" : "=l"(r) : "f"(lo), "f"(hi)); return r; }
__device__ __forceinline__ void unpack2(u64 v, float& lo, float& hi){ asm("mov.b64 {%0,%1},%2;" : "=f"(lo), "=f"(hi) : "l"(v)); }
__device__ __forceinline__ void ffma2(u64& d, u64 a, u64 b){ asm("fma.rn.f32x2 %0,%1,%2,%0;" : "+l"(d) : "l"(a), "l"(b)); }

__device__ float g_Wcat[CS * PW];
__device__ float g_proj[LL * PW];   // [q 0|k 192|v 384|qp 576|kp 720|vp 864]
__device__ float g_R[LL * 9];
__device__ float g_t[LL * 3];
__device__ float g_coef[12];
__device__ float g_qpp[LL * 144];
__device__ float g_kT[192 * LL];
__device__ float g_vT[192 * LL];
__device__ float g_kppT[144 * LL];
__device__ float g_vppT[288 * LL];
__device__ float g_Bt[12 * LL * LL];    // bias logits, head-major [h][i*512+j]
__device__ float g_shid[LL * SH];
__device__ float g_parts[6 * LL * CS];
__device__ float g_s1[LL * CS];
__device__ float g_h1[LL * CS];
__device__ float g_h2[LL * CS];

// merged: weight packing + quat prep + bias GEMM (128 rows per CTA, 2048 CTAs)
__global__ __launch_bounds__(256) void prep_bias(
    const float* __restrict__ z, const float* __restrict__ Wb,
    const float* __restrict__ Wq, const float* __restrict__ Wk,
    const float* __restrict__ Wv, const float* __restrict__ Wqp,
    const float* __restrict__ Wkp, const float* __restrict__ Wvp,
    const float* __restrict__ quat, const float* __restrict__ trsl,
    const float* __restrict__ scale)
{
    int tid = threadIdx.x;
    int gid = blockIdx.x * 256 + tid;

    if (gid < CS * PW) {
        int r = gid / PW, c = gid - r * PW;
        float v;
        if      (c < 192)  v = Wq [r*192 + c];
        else if (c < 384)  v = Wk [r*192 + c-192];
        else if (c < 576)  v = Wv [r*192 + c-384];
        else if (c < 720)  v = Wqp[r*144 + c-576];
        else if (c < 864)  v = Wkp[r*144 + c-720];
        else               v = Wvp[r*288 + c-864];
        g_Wcat[gid] = v;
    }
    if (gid < LL) {
        float w = quat[gid*4], x = quat[gid*4+1], y = quat[gid*4+2], zz = quat[gid*4+3];
        float inv = rsqrtf(w*w + x*x + y*y + zz*zz);
        w *= inv; x *= inv; y *= inv; zz *= inv;
        float* R = g_R + gid*9;
        R[0]=1.f-2.f*(y*y+zz*zz); R[1]=2.f*(x*y-w*zz);     R[2]=2.f*(x*zz+w*y);
        R[3]=2.f*(x*y+w*zz);      R[4]=1.f-2.f*(x*x+zz*zz); R[5]=2.f*(y*zz-w*x);
        R[6]=2.f*(x*zz-w*y);      R[7]=2.f*(y*zz+w*x);      R[8]=1.f-2.f*(x*x+y*y);
        g_t[gid*3]=trsl[gid*3]; g_t[gid*3+1]=trsl[gid*3+1]; g_t[gid*3+2]=trsl[gid*3+2];
    }
    if (gid < 12) g_coef[gid] = 0.5f * WCC * log1pf(expf(scale[gid]));

    __shared__ u64 sW[CZ * 6];          // 12 KB
    __shared__ float sAz[128][33];      // 16.9 KB
    int row0 = blockIdx.x * 128;
    int q = tid & 127, hp = tid >> 7;

    for (int x = tid; x < CZ*6; x += 256) {
        int c = x / 6, p = x - c*6;
        sW[x] = pack2(Wb[c*12 + 2*p], Wb[c*12 + 2*p + 1]);
    }

    u64 acc[3] = {};
    for (int ch = 0; ch < 8; ch++) {
        __syncthreads();
        #pragma unroll
        for (int t0 = 0; t0 < 4; t0++) {
            int idx = tid + t0 * 256;
            int row = idx >> 3, c4 = idx & 7;
            float4 v = *(const float4*)(z + (size_t)(row0 + row) * CZ + ch*32 + c4*4);
            sAz[row][c4*4+0] = v.x; sAz[row][c4*4+1] = v.y;
            sAz[row][c4*4+2] = v.z; sAz[row][c4*4+3] = v.w;
        }
        __syncthreads();
        #pragma unroll 4
        for (int c = 0; c < 32; c++) {
            int cc = ch*32 + c;
            u64 d0 = dup2(sAz[q][c]);
            ffma2(acc[0], d0, sW[cc*6 + hp*3 + 0]);
            ffma2(acc[1], d0, sW[cc*6 + hp*3 + 1]);
            ffma2(acc[2], d0, sW[cc*6 + hp*3 + 2]);
        }
    }
    #pragma unroll
    for (int p = 0; p < 3; p++) {
        float lo, hi;
        unpack2(acc[p], lo, hi);
        g_Bt[(size_t)(hp*6+2*p  )*(LL*LL) + row0 + q] = lo;
        g_Bt[(size_t)(hp*6+2*p+1)*(LL*LL) + row0 + q] = hi;
    }
}

__global__ void transform()
{
    int i = blockIdx.x, pt = threadIdx.x;   // 384 threads
    if (pt < 192) g_kT[pt * LL + i] = g_proj[(size_t)i*PW + 192 + pt];
    else          g_vT[(pt-192) * LL + i] = g_proj[(size_t)i*PW + 384 + (pt-192)];
    if (pt >= 192) return;
    const float* R = g_R + i*9;
    const float* t = g_t + i*3;
    const float* src;
    if (pt < 48)      src = g_proj + (size_t)i*PW + 576 + pt*3;
    else if (pt < 96) src = g_proj + (size_t)i*PW + 720 + (pt-48)*3;
    else              src = g_proj + (size_t)i*PW + 864 + (pt-96)*3;
    float px = src[0], py = src[1], pz = src[2];
    float ox = R[0]*px + R[1]*py + R[2]*pz + t[0];
    float oy = R[3]*px + R[4]*py + R[5]*pz + t[1];
    float oz = R[6]*px + R[7]*py + R[8]*pz + t[2];
    if (pt < 48) {
        float* d = g_qpp + i*144 + pt*3;
        d[0] = ox; d[1] = oy; d[2] = oz;
    } else if (pt < 96) {
        int p = pt - 48;
        g_kppT[(p*3+0)*LL + i] = ox;
        g_kppT[(p*3+1)*LL + i] = oy;
        g_kppT[(p*3+2)*LL + i] = oz;
    } else {
        int p = pt - 96;
        g_vppT[(p*3+0)*LL + i] = ox;
        g_vppT[(p*3+1)*LL + i] = oy;
        g_vppT[(p*3+2)*LL + i] = oz;
    }
}

// 128x64 tile GEMM, 256 threads, 8x4/thread, A pre-duplicated f32x2 in smem
__global__ __launch_bounds__(256) void gemm128(const float* __restrict__ A,
                                               const float* __restrict__ B,
                                               float* __restrict__ C,
                                               int lda, int ldb, int ldc,
                                               int kSlice, int K, int partStride)
{
    __shared__ u64 As[16][128];
    __shared__ float Bs[16][64];
    int n0 = blockIdx.x * 64, m0 = blockIdx.y * 128;
    int k0 = blockIdx.z * kSlice;
    int kend = min(K, k0 + kSlice);
    float* Cc = C + (size_t)blockIdx.z * partStride;
    int tid = threadIdx.x;
    int tx = tid & 15, ty = tid >> 4;
    u64 acc[8][2] = {};
    for (int kt = k0; kt < kend; kt += 16) {
        #pragma unroll
        for (int half = 0; half < 2; half++) {
            int f = tid + half * 256;
            int row = f >> 2, kq = (f & 3) << 2;
            float4 av = *(const float4*)(A + (size_t)(m0 + row) * lda + kt + kq);
            As[kq+0][row] = dup2(av.x);
            As[kq+1][row] = dup2(av.y);
            As[kq+2][row] = dup2(av.z);
            As[kq+3][row] = dup2(av.w);
        }
        {
            int k = tid >> 4, nq = (tid & 15) << 2;
            *(float4*)&Bs[k][nq] = *(const float4*)(B + (size_t)(kt + k) * ldb + n0 + nq);
        }
        __syncthreads();
        #pragma unroll
        for (int kk = 0; kk < 16; kk++) {
            u64 a[8];
            *(ulonglong2*)&a[0] = *(ulonglong2*)&As[kk][ty*8+0];
            *(ulonglong2*)&a[2] = *(ulonglong2*)&As[kk][ty*8+2];
            *(ulonglong2*)&a[4] = *(ulonglong2*)&As[kk][ty*8+4];
            *(ulonglong2*)&a[6] = *(ulonglong2*)&As[kk][ty*8+6];
            ulonglong2 b2 = *(ulonglong2*)&Bs[kk][tx << 2];
            #pragma unroll
            for (int m = 0; m < 8; m++) {
                ffma2(acc[m][0], a[m], b2.x);
                ffma2(acc[m][1], a[m], b2.y);
            }
        }
        __syncthreads();
    }
    #pragma unroll
    for (int m = 0; m < 8; m++) {
        ulonglong2 st; st.x = acc[m][0]; st.y = acc[m][1];
        *(ulonglong2*)(Cc + (size_t)(m0 + ty*8 + m) * ldc + n0 + (tx << 2)) = st;
    }
}

__global__ void combine(const float* __restrict__ parts, int nparts, int partStride,
                        const float* __restrict__ bias, float* __restrict__ out,
                        int total, int N, int relu)
{
    int idx = blockIdx.x * blockDim.x + threadIdx.x;
    if (idx >= total) return;
    float v = parts[idx];
    for (int p = 1; p < nparts; p++) v += parts[(size_t)p * partStride + idx];
    if (bias) v += bias[idx % N];
    if (relu) v = fmaxf(v, 0.f);
    out[idx] = v;
}

__global__ void ln_combine(const float* __restrict__ parts, int nparts, int partStride,
                           const float* __restrict__ bias, const float* __restrict__ resid,
                           const float* __restrict__ gg, const float* __restrict__ bb,
                           float* __restrict__ out)
{
    int i = blockIdx.x, t = threadIdx.x;   // 128 threads
    float v[3];
    #pragma unroll
    for (int k = 0; k < 3; k++) {
        int c = t + k * 128;
        size_t off = (size_t)i * CS + c;
        float x = parts[off];
        for (int p = 1; p < nparts; p++) x += parts[(size_t)p * partStride + off];
        v[k] = x + bias[c] + resid[off];
    }
    float s = v[0]+v[1]+v[2], q = v[0]*v[0]+v[1]*v[1]+v[2]*v[2];
    #pragma unroll
    for (int o = 16; o; o >>= 1) {
        s += __shfl_xor_sync(0xffffffffu, s, o);
        q += __shfl_xor_sync(0xffffffffu, q, o);
    }
    __shared__ float ss[4], sq[4];
    int w = t >> 5, lane = t & 31;
    if (lane == 0) { ss[w] = s; sq[w] = q; }
    __syncthreads();
    if (t == 0) {
        float S = ss[0]+ss[1]+ss[2]+ss[3], Q = sq[0]+sq[1]+sq[2]+sq[3];
        float m = S * (1.f/CS);
        ss[0] = m; sq[0] = rsqrtf(Q*(1.f/CS) - m*m + 1e-5f);
    }
    __syncthreads();
    float m = ss[0], r = sq[0];
    float* o = out + (size_t)i * CS;
    #pragma unroll
    for (int k = 0; k < 3; k++) {
        int c = t + k * 128;
        o[c] = (v[k]-m)*r*gg[c] + bb[c];
    }
}

// attention fused: vectorized logits + softmax + ov/ovp + op(a^T@z); 512 threads
__global__ __launch_bounds__(512) void attn(const float* __restrict__ z)
{
    __shared__ float sA[12 * LL];     // 24 KB
    __shared__ float sq[192], sqpp[144], sR[9], st3[3], scoef[12], sOVP[288];

    int i = blockIdx.x, tid = threadIdx.x;
    int lane = tid & 31, w = tid >> 5;     // 16 warps

    if (tid < 192) sq[tid] = g_proj[(size_t)i * PW + tid];
    if (tid < 144) sqpp[tid] = g_qpp[i*144 + tid];
    if (tid < 9)   sR[tid] = g_R[i*9 + tid];
    if (tid < 3)   st3[tid] = g_t[i*3 + tid];
    if (tid < 12)  scoef[tid] = g_coef[tid];
    __syncthreads();

    // ---- logits, float4 over j: 4 heads x 128 j-quads per iteration ----
    {
        int hb = tid >> 7;              // 0..3
        int j0 = (tid & 127) << 2;      // 0,4,...,508
        #pragma unroll 1
        for (int hh = 0; hh < 3; hh++) {
            int h = hh * 4 + hb;
            float4 qk = make_float4(0.f,0.f,0.f,0.f);
            const float* kTb = g_kT + (size_t)(h*16)*LL + j0;
            #pragma unroll
            for (int d = 0; d < 16; d++) {
                float qv = sq[h*16+d];
                float4 kv = *(const float4*)(kTb + d*LL);
                qk.x = fmaf(qv, kv.x, qk.x); qk.y = fmaf(qv, kv.y, qk.y);
                qk.z = fmaf(qv, kv.z, qk.z); qk.w = fmaf(qv, kv.w, qk.w);
            }
            float4 d2 = make_float4(0.f,0.f,0.f,0.f);
            const float* kpb = g_kppT + (size_t)(h*12)*LL + j0;
            #pragma unroll
            for (int e = 0; e < 12; e++) {
                float qp = sqpp[h*12+e];
                float4 kp = *(const float4*)(kpb + e*LL);
                float a = qp-kp.x, b = qp-kp.y, c = qp-kp.z, dd = qp-kp.w;
                d2.x = fmaf(a,a,d2.x); d2.y = fmaf(b,b,d2.y);
                d2.z = fmaf(c,c,d2.z); d2.w = fmaf(dd,dd,d2.w);
            }
            float4 bh = *(const float4*)(g_Bt + (size_t)h * (LL*LL) + (size_t)i * LL + j0);
            float cf = scoef[h];
            float4 o;
            o.x = WLL * (qk.x * 0.25f + bh.x - cf * d2.x);
            o.y = WLL * (qk.y * 0.25f + bh.y - cf * d2.y);
            o.z = WLL * (qk.z * 0.25f + bh.z - cf * d2.z);
            o.w = WLL * (qk.w * 0.25f + bh.w - cf * d2.w);
            *(float4*)&sA[h*LL + j0] = o;
        }
    }
    __syncthreads();

    // ---- softmax per head: warp w handles head w ----
    if (w < 12) {
        float* row = sA + w * LL;
        float m = -1e30f;
        for (int j = lane; j < LL; j += 32) m = fmaxf(m, row[j]);
        #pragma unroll
        for (int o = 16; o; o >>= 1) m = fmaxf(m, __shfl_xor_sync(0xffffffffu, m, o));
        float sum = 0.f;
        for (int j = lane; j < LL; j += 32) {
            float e = __expf(row[j] - m);
            row[j] = e; sum += e;
        }
        #pragma unroll
        for (int o = 16; o; o >>= 1) sum += __shfl_xor_sync(0xffffffffu, sum, o);
        float inv = 1.f / sum;
        for (int j = lane; j < LL; j += 32) row[j] *= inv;
    }
    __syncthreads();

    // ---- ov (16 dims) + ovp_g (24 dims): warp-cooperative over j ----
    for (int task = w; task < 480; task += 16) {
        int h = task / 40, dim = task % 40;
        const float* src = (dim < 16) ? g_vT + (size_t)(h*16+dim)*LL
                                      : g_vppT + (size_t)(h*24+dim-16)*LL;
        const float* ap = sA + h * LL;
        float acc = 0.f;
        #pragma unroll
        for (int it = 0; it < 4; it++) {
            int j = (lane + it*32) * 4;
            float4 vv = *(const float4*)(src + j);
            float4 aa = *(const float4*)(ap + j);
            acc = fmaf(aa.x,vv.x, fmaf(aa.y,vv.y, fmaf(aa.z,vv.z, fmaf(aa.w,vv.w, acc))));
        }
        #pragma unroll
        for (int o = 16; o; o >>= 1) acc += __shfl_xor_sync(0xffffffffu, acc, o);
        if (lane == 0) {
            float* orow = g_shid + (size_t)i * SH + h * 304;
            if (dim < 16) orow[256+dim] = acc;
            else          sOVP[h*24 + dim-16] = acc;
        }
    }
    __syncthreads();

    // ---- ovp = R^T (ovp_g - t), norms ----
    if (tid < 96) {
        int h = tid >> 3, vv = tid & 7;
        float gx = sOVP[h*24 + vv*3 + 0] - st3[0];
        float gy = sOVP[h*24 + vv*3 + 1] - st3[1];
        float gz = sOVP[h*24 + vv*3 + 2] - st3[2];
        float lx = sR[0]*gx + sR[3]*gy + sR[6]*gz;
        float ly = sR[1]*gx + sR[4]*gy + sR[7]*gz;
        float lz = sR[2]*gx + sR[5]*gy + sR[8]*gz;
        float* orow = g_shid + (size_t)i * SH + h * 304;
        orow[272 + vv*3 + 0] = lx;
        orow[272 + vv*3 + 1] = ly;
        orow[272 + vv*3 + 2] = lz;
        orow[296 + vv] = sqrtf(lx*lx + ly*ly + lz*lz);
    }

    // ---- op = a^T @ z : 4 head-triples x 128 col-pairs, f32x2 ----
    {
        int h0 = (tid >> 7) * 3;
        int cc = (tid & 127) * 2;
        const float* zp = z + (size_t)i * LL * CZ + cc;
        const float* a0p = sA + (h0+0) * LL;
        const float* a1p = sA + (h0+1) * LL;
        const float* a2p = sA + (h0+2) * LL;
        u64 acc[3] = {};
        for (int j = 0; j < LL; j += 4) {
            u64 zv[4];
            #pragma unroll
            for (int u = 0; u < 4; u++)
                zv[u] = *(const u64*)(zp + (size_t)(j+u) * CZ);
            float4 a0 = *(const float4*)(a0p + j);
            float4 a1 = *(const float4*)(a1p + j);
            float4 a2 = *(const float4*)(a2p + j);
            float a0v[4] = {a0.x,a0.y,a0.z,a0.w};
            float a1v[4] = {a1.x,a1.y,a1.z,a1.w};
            float a2v[4] = {a2.x,a2.y,a2.z,a2.w};
            #pragma unroll
            for (int u = 0; u < 4; u++) {
                ffma2(acc[0], zv[u], dup2(a0v[u]));
                ffma2(acc[1], zv[u], dup2(a1v[u]));
                ffma2(acc[2], zv[u], dup2(a2v[u]));
            }
        }
        float* orow = g_shid + (size_t)i * SH;
        #pragma unroll
        for (int hh = 0; hh < 3; hh++)
            *(u64*)(orow + (h0+hh)*304 + cc) = acc[hh];
    }
}

extern "C" void kernel_launch(void* const* d_in, const int* in_sizes, int n_in,
                              void* d_out, int out_size)
{
    const float* s    = (const float*)d_in[0];
    const float* z    = (const float*)d_in[1];
    const float* quat = (const float*)d_in[2];
    const float* trsl = (const float*)d_in[3];
    const float* Wq   = (const float*)d_in[4];
    const float* Wk   = (const float*)d_in[5];
    const float* Wv   = (const float*)d_in[6];
    const float* Wqp  = (const float*)d_in[7];
    const float* Wkp  = (const float*)d_in[8];
    const float* Wvp  = (const float*)d_in[9];
    const float* Wb   = (const float*)d_in[10];
    const float* Ws   = (const float*)d_in[11];
    const float* bs   = (const float*)d_in[12];
    const float* scale= (const float*)d_in[13];
    const float* g1   = (const float*)d_in[14];
    const float* b1   = (const float*)d_in[15];
    const float* Wm1  = (const float*)d_in[16];
    const float* bm1  = (const float*)d_in[17];
    const float* Wm2  = (const float*)d_in[18];
    const float* bm2  = (const float*)d_in[19];
    const float* Wm3  = (const float*)d_in[20];
    const float* bm3  = (const float*)d_in[21];
    const float* g2   = (const float*)d_in[22];
    const float* b2   = (const float*)d_in[23];
    float* out = (float*)d_out;

    void *pWcat, *pProj, *pShid, *pParts, *pS1, *pH1, *pH2;
    cudaGetSymbolAddress(&pWcat,  g_Wcat);
    cudaGetSymbolAddress(&pProj,  g_proj);
    cudaGetSymbolAddress(&pShid,  g_shid);
    cudaGetSymbolAddress(&pParts, g_parts);
    cudaGetSymbolAddress(&pS1,    g_s1);
    cudaGetSymbolAddress(&pH1,    g_h1);
    cudaGetSymbolAddress(&pH2,    g_h2);
    float* Wcat = (float*)pWcat;  float* proj = (float*)pProj;
    float* shid = (float*)pShid;  float* parts = (float*)pParts;
    float* s1 = (float*)pS1;      float* h1 = (float*)pH1;
    float* h2 = (float*)pH2;

    const int TOT = LL * CS;

    prep_bias<<<2048, 256>>>(z, Wb, Wq, Wk, Wv, Wqp, Wkp, Wvp, quat, trsl, scale);
    gemm128<<<dim3(PW/64, LL/128, 1), 256>>>(s, Wcat, proj, CS, PW, PW, CS, CS, 0);
    transform<<<LL, 384>>>();
    // 4: fused attn (+op)  <- profiled launch
    attn<<<LL, 512>>>(z);
    gemm128<<<dim3(CS/64, LL/128, 6), 256>>>(shid, Ws, parts, SH, CS, CS, SH/6, SH, TOT);
    ln_combine<<<LL, 128>>>(parts, 6, TOT, bs, s, g1, b1, s1);
    gemm128<<<dim3(CS/64, LL/128, 6), 256>>>(s1, Wm1, parts, CS, CS, CS, CS/6, CS, TOT);
    combine<<<(TOT+255)/256, 256>>>(parts, 6, TOT, bm1, h1, TOT, CS, 1);
    gemm128<<<dim3(CS/64, LL/128, 6), 256>>>(h1, Wm2, parts, CS, CS, CS, CS/6, CS, TOT);
    combine<<<(TOT+255)/256, 256>>>(parts, 6, TOT, bm2, h2, TOT, CS, 1);
    gemm128<<<dim3(CS/64, LL/128, 6), 256>>>(h2, Wm3, parts, CS, CS, CS, CS/6, CS, TOT);
    ln_combine<<<LL, 128>>>(parts, 6, TOT, bm3, s1, g2, b2, out);
}